// round 14
// baseline (speedup 1.0000x reference)
#include <cuda_runtime.h>
#include <cuda_fp16.h>
#include <cstdint>
#include <math.h>

// Problem constants
#define HSZ    4096
#define NHEADS 32
#define NKV    8
#define HD     128
#define SEQ    4096
#define BATCH  2
#define MTOT   (BATCH * SEQ)   // 8192
#define KD     4096
#define NQKV   6144            // 4096 + 1024 + 1024

// ---------------- scratch (device globals) ---------------------------------
__device__ __half g_Xh[(size_t)MTOT * HSZ];     // fp16 hidden_states
__device__ __half g_Wqkvh[(size_t)KD * NQKV];   // packed [K][6144] fp16
__device__ __half g_Woh[(size_t)KD * HSZ];      // Wo fp16 [K][N]
__device__ __half g_QKVh[(size_t)MTOT * NQKV];  // q|k|v per token (fp16)
__device__ __half g_Yh[(size_t)MTOT * HSZ];     // attn out fp16
__device__ float  g_sin[SEQ * 64];
__device__ float  g_cos[SEQ * 64];

// ---------------- helpers ---------------------------------------------------
__device__ __forceinline__ uint32_t s2u(const void* p) {
    uint32_t a;
    asm("{ .reg .u64 t; cvta.to.shared.u64 t, %1; cvt.u32.u64 %0, t; }"
        : "=r"(a) : "l"(p));
    return a;
}
__device__ __forceinline__ void cpa16(uint32_t dst, const void* src) {
    asm volatile("cp.async.cg.shared.global [%0], [%1], 16;" :: "r"(dst), "l"(src) : "memory");
}
__device__ __forceinline__ void cpa_commit() {
    asm volatile("cp.async.commit_group;" ::: "memory");
}
template<int N_>
__device__ __forceinline__ void cpa_wait() {
    asm volatile("cp.async.wait_group %0;" :: "n"(N_) : "memory");
}
__device__ __forceinline__ void ldmA(uint32_t r[4], uint32_t addr) {
    asm volatile("ldmatrix.sync.aligned.m8n8.x4.shared.b16 {%0,%1,%2,%3}, [%4];"
                 : "=r"(r[0]), "=r"(r[1]), "=r"(r[2]), "=r"(r[3]) : "r"(addr));
}
__device__ __forceinline__ void ldmB4(uint32_t r[4], uint32_t addr) {
    asm volatile("ldmatrix.sync.aligned.m8n8.x4.trans.shared.b16 {%0,%1,%2,%3}, [%4];"
                 : "=r"(r[0]), "=r"(r[1]), "=r"(r[2]), "=r"(r[3]) : "r"(addr));
}
__device__ __forceinline__ void mma16816(float c[4], const uint32_t a[4],
                                         uint32_t b0, uint32_t b1) {
    asm("mma.sync.aligned.m16n8k16.row.col.f32.f16.f16.f32 "
        "{%0,%1,%2,%3}, {%4,%5,%6,%7}, {%8,%9}, {%0,%1,%2,%3};"
        : "+f"(c[0]), "+f"(c[1]), "+f"(c[2]), "+f"(c[3])
        : "r"(a[0]), "r"(a[1]), "r"(a[2]), "r"(a[3]), "r"(b0), "r"(b1));
}

// ---------------- RoPE helpers ----------------------------------------------
// accurate sincos of a double argument (|x| < 2^26), explicit DFMA only
__device__ __forceinline__ void dsincos(double x, float* so, float* co) {
    double n = rint(x * 0.63661977236758138);       // x * 2/pi
    long long qi = (long long)n;
    double r = fma(n, -1.5707963267948966, x);      // pi/2 hi
    r = fma(n, -6.123233995736766e-17, r);          // pi/2 lo
    double r2 = r * r;
    double p = fma(r2, 2.7557319223985893e-06, -1.9841269841269841e-04);
    p = fma(r2, p, 8.3333333333333332e-03);
    p = fma(r2, p, -1.6666666666666666e-01);
    double sinr = fma(r * r2, p, r);
    double q = fma(r2, -2.7557319223985888e-07, 2.4801587301587302e-05);
    q = fma(r2, q, -1.3888888888888889e-03);
    q = fma(r2, q, 4.1666666666666666e-02);
    q = fma(r2, q, -0.5);
    double cosr = fma(r2, q, 1.0);
    switch ((int)(qi & 3)) {
        case 0: *so = (float)sinr;  *co = (float)cosr;  break;
        case 1: *so = (float)cosr;  *co = (float)-sinr; break;
        case 2: *so = (float)-sinr; *co = (float)-cosr; break;
        default:*so = (float)-cosr; *co = (float)sinr;  break;
    }
}

// ---------------- fused prep: f2h(hs) | f2h(Wo) | pack_qkv | rope -----------
// block ranges: [0,1024) hs->Xh, [1024,1536) Wo->Woh, [1536,2304) pack, [2304,2560) rope
#define PREP_BLOCKS 2560

__device__ __forceinline__ void f2h_range(const float* __restrict__ src,
                                          __half* __restrict__ dst,
                                          size_t n4, int blk, int nblk) {
    size_t stride = (size_t)nblk * 256;
    for (size_t i = (size_t)blk * 256 + threadIdx.x; i < n4; i += stride) {
        float4 v = reinterpret_cast<const float4*>(src)[i];
        __half2 h0 = __floats2half2_rn(v.x, v.y);
        __half2 h1 = __floats2half2_rn(v.z, v.w);
        uint2 u;
        u.x = *reinterpret_cast<uint32_t*>(&h0);
        u.y = *reinterpret_cast<uint32_t*>(&h1);
        *reinterpret_cast<uint2*>(dst + i * 4) = u;
    }
}

__global__ __launch_bounds__(256)
void prep_kernel(const float* __restrict__ hs, const float* __restrict__ Wq,
                 const float* __restrict__ Wk, const float* __restrict__ Wv,
                 const float* __restrict__ Wo)
{
    const int b = blockIdx.x;
    if (b < 1024) {
        f2h_range(hs, g_Xh, (size_t)MTOT * HSZ / 4, b, 1024);
    } else if (b < 1536) {
        f2h_range(Wo, g_Woh, (size_t)KD * HSZ / 4, b - 1024, 512);
    } else if (b < 2304) {
        const int blk = b - 1536;
        const size_t total = (size_t)KD * NQKV / 4;
        size_t stride = (size_t)768 * 256;
        for (size_t i = (size_t)blk * 256 + threadIdx.x; i < total; i += stride) {
            int row = (int)(i / (NQKV / 4));
            int col = (int)(i % (NQKV / 4)) * 4;
            float4 v;
            if (col < 4096)
                v = *reinterpret_cast<const float4*>(Wq + (size_t)row * 4096 + col);
            else if (col < 5120)
                v = *reinterpret_cast<const float4*>(Wk + (size_t)row * 1024 + (col - 4096));
            else
                v = *reinterpret_cast<const float4*>(Wv + (size_t)row * 1024 + (col - 5120));
            __half2 h0 = __floats2half2_rn(v.x, v.y);
            __half2 h1 = __floats2half2_rn(v.z, v.w);
            uint2 u;
            u.x = *reinterpret_cast<uint32_t*>(&h0);
            u.y = *reinterpret_cast<uint32_t*>(&h1);
            *reinterpret_cast<uint2*>(g_Wqkvh + (size_t)row * NQKV + col) = u;
        }
    } else {
        // rope: compute emb locally (bit-identical double pow), then table slice
        __shared__ float emb_s[64];
        if (threadIdx.x < 64) {
            int d  = threadIdx.x;
            int k2 = d & ~1;
            float e = (float)k2 / 64.0f;
            emb_s[d] = (float)pow(10000.0, (double)e);
        }
        __syncthreads();
        const int blk = b - 2304;                      // 0..255
        int idx = blk * 1024 + threadIdx.x;            // covers SEQ*64 via 4 steps
        #pragma unroll
        for (int t = 0; t < 4; t++, idx += 256) {
            int pos = idx >> 6, d = idx & 63;
            float emb  = emb_s[d];
            float freq = (float)pos * emb;             // single fp32 rounding, like jax
            float s, c;
            dsincos((double)freq, &s, &c);
            g_sin[idx] = s;
            g_cos[idx] = c;
        }
    }
}

// ---------------- persistent pipelined FP16 GEMM (fp32 accumulate) -----------
// C[M,N] = A[M,K] @ B[K,N]. fp16 in. K = 4096.
// CTA tile 128x256, 512 threads (16 warps, 2x8), warp tile 64x32, 3 stages.
// Persistent: grid=148; cp.async ring runs continuously across tile boundaries.
#define BM 128
#define BN 256
#define BK 64
#define NTHR 512
#define STAGES 3
#define PA 72                          // A smem row pitch (halves)
#define PB 264                         // B smem row pitch (halves)
#define A_HALVES (BM * PA)             // 9216
#define B_HALVES (BK * PB)             // 16896
#define STAGE_HALVES (A_HALVES + B_HALVES)
#define STAGE_BYTES (STAGE_HALVES * 2)       // 52224
#define GEMM_DYN (STAGES * STAGE_BYTES)      // 156672
#define NT (KD / BK)                   // 64
#define GEMM_GRID 148

template<bool HALF_OUT>
__global__ __launch_bounds__(NTHR, 1)
void gemm_f16(const __half* __restrict__ A, const __half* __restrict__ B,
              void* __restrict__ Cv, int N)
{
    extern __shared__ __half dynh[];
    const uint32_t sbase = s2u(dynh);

    const int tid  = threadIdx.x;
    const int lane = tid & 31, warp = tid >> 5;
    const int warpM = warp & 1;        // 64-row slab
    const int warpN = warp >> 1;       // 0..7 -> 32-col slab
    const int g  = lane >> 2;
    const int tg = lane & 3;

    const int n_tiles = N / BN;
    const int ntiles  = (MTOT / BM) * n_tiles;
    const int per = 8 * n_tiles;       // L2-friendly grouping of 8 m-tiles

    // tile index -> (rowBase, colBase)
    auto tile_mn = [&](int t, int& rowB, int& colB) {
        int gblk = t / per, rr0 = t % per;
        rowB = (gblk * 8 + (rr0 & 7)) * BM;
        colB = (rr0 >> 3) * BN;
    };

    // issue K-tile kt of tile at (rowB, colB) into ring slot s
    auto issue = [&](int rowB, int colB, int kt, int s) {
        const uint32_t sa = sbase + s * STAGE_BYTES;
        const uint32_t sb = sa + A_HALVES * 2;
        const __half* Ag = A + (size_t)rowB * KD;
        #pragma unroll
        for (int i = 0; i < 2; i++) {          // A: 128 rows x 128B = 1024 chunks
            int ch = tid + i * NTHR;
            int r = ch >> 3, c8 = ch & 7;
            cpa16(sa + (r * PA + c8 * 8) * 2,
                  Ag + (size_t)r * KD + kt * BK + c8 * 8);
        }
        #pragma unroll
        for (int i = 0; i < 4; i++) {          // B: 64 rows x 512B = 2048 chunks
            int ch = tid + i * NTHR;
            int r = ch >> 5, c8 = ch & 31;
            cpa16(sb + (r * PB + c8 * 8) * 2,
                  B + (size_t)(kt * BK + r) * N + colB + c8 * 8);
        }
    };

    // ldmatrix per-lane byte offsets
    const uint32_t a_off = ((warpM * 64 + (lane & 15)) * PA + (lane >> 4) * 8) * 2;
    const uint32_t b_off = ((lane & 15) * PB + warpN * 32 + (lane >> 4) * 8) * 2;

    // prologue: first tile's stages 0,1 into ring slots 0,1
    int rb = 0;                         // ring base for current tile
    {
        int r0, c0;
        if (blockIdx.x < ntiles) {
            tile_mn(blockIdx.x, r0, c0);
            issue(r0, c0, 0, 0); cpa_commit();
            issue(r0, c0, 1, 1); cpa_commit();
        }
    }

    for (int t = blockIdx.x; t < ntiles; t += GEMM_GRID) {
        int rowBase, colBase;
        tile_mn(t, rowBase, colBase);
        const int tn = t + GEMM_GRID;
        const bool has_next = tn < ntiles;
        int rn = 0, cn = 0;
        if (has_next) tile_mn(tn, rn, cn);

        float c[4][4][4];
        #pragma unroll
        for (int m2 = 0; m2 < 4; m2++)
            #pragma unroll
            for (int n2 = 0; n2 < 4; n2++)
                #pragma unroll
                for (int i = 0; i < 4; i++) c[m2][n2][i] = 0.f;

        for (int kt = 0; kt < NT; kt++) {
            cpa_wait<STAGES - 2>();
            __syncthreads();

            const int gn = kt + STAGES - 1;          // global lookahead
            const int sn = (rb + gn) % STAGES;
            if (gn < NT)            issue(rowBase, colBase, gn, sn);
            else if (has_next)      issue(rn, cn, gn - NT, sn);
            cpa_commit();

            const int slot = (rb + kt) % STAGES;
            const uint32_t sa = sbase + slot * STAGE_BYTES;
            const uint32_t sb = sa + A_HALVES * 2;

            #pragma unroll
            for (int ks = 0; ks < 4; ks++) {       // 4 x k16
                uint32_t af[4][4], bf[2][4];
                #pragma unroll
                for (int m2 = 0; m2 < 4; m2++)
                    ldmA(af[m2], sa + a_off + (m2 * 16 * PA + ks * 16) * 2);
                #pragma unroll
                for (int n4 = 0; n4 < 2; n4++)
                    ldmB4(bf[n4], sb + b_off + (ks * 16 * PB + n4 * 16) * 2);
                #pragma unroll
                for (int m2 = 0; m2 < 4; m2++)
                    #pragma unroll
                    for (int n4 = 0; n4 < 2; n4++) {
                        mma16816(c[m2][n4 * 2    ], af[m2], bf[n4][0], bf[n4][1]);
                        mma16816(c[m2][n4 * 2 + 1], af[m2], bf[n4][2], bf[n4][3]);
                    }
            }
        }

        // epilogue (register-direct stores; overlaps next tile's in-flight loads)
        #pragma unroll
        for (int m2 = 0; m2 < 4; m2++) {
            #pragma unroll
            for (int n2 = 0; n2 < 4; n2++) {
                int row = rowBase + warpM * 64 + m2 * 16 + g;
                int col = colBase + warpN * 32 + n2 * 8 + tg * 2;
                if (HALF_OUT) {
                    __half* C = (__half*)Cv;
                    __half2 v01 = __floats2half2_rn(c[m2][n2][0], c[m2][n2][1]);
                    __half2 v23 = __floats2half2_rn(c[m2][n2][2], c[m2][n2][3]);
                    *reinterpret_cast<__half2*>(C + (size_t)row * N + col)       = v01;
                    *reinterpret_cast<__half2*>(C + (size_t)(row + 8) * N + col) = v23;
                } else {
                    float* C = (float*)Cv;
                    float2 v01 = make_float2(c[m2][n2][0], c[m2][n2][1]);
                    float2 v23 = make_float2(c[m2][n2][2], c[m2][n2][3]);
                    *reinterpret_cast<float2*>(C + (size_t)row * N + col)       = v01;
                    *reinterpret_cast<float2*>(C + (size_t)(row + 8) * N + col) = v23;
                }
            }
        }

        rb = (rb + NT) % STAGES;        // 64 % 3 == 1: ring base advances
    }
}

// ---------------- RoPE + per-token GQA attention (R10 exact) -----------------
__global__ __launch_bounds__(256)
void attn_kernel()
{
    const int tok = blockIdx.x;
    const int pos = tok & (SEQ - 1);
    const int tid = threadIdx.x;

    __shared__ float qs[NHEADS][HD + 4];
    __shared__ float ks[NKV][HD + 4];
    __shared__ float vs[NKV][HD + 4];
    __shared__ float ps[NHEADS][NKV];

    const float* sp = g_sin + pos * 64;
    const float* cp = g_cos + pos * 64;
    const __half* base = g_QKVh + (size_t)tok * NQKV;

    // K/V: NKV*32 threads handle 2 dims each via __half2
    for (int idx = tid; idx < NKV * 32; idx += 256) {
        int j = idx >> 5, dd = (idx & 31) * 2;
        const __half* kptr = base + 4096 + j * HD;
        const __half* vptr = base + 5120 + j * HD;
        __half2 klo = *reinterpret_cast<const __half2*>(kptr + dd);
        __half2 khi = *reinterpret_cast<const __half2*>(kptr + 64 + dd);
        __half2 vlo = *reinterpret_cast<const __half2*>(vptr + dd);
        __half2 vhi = *reinterpret_cast<const __half2*>(vptr + 64 + dd);
        #pragma unroll
        for (int u = 0; u < 2; u++) {
            int d = dd + u;
            float s = sp[d], co = cp[d];
            float k0 = __half2float(u ? __high2half(klo) : __low2half(klo));
            float k1 = __half2float(u ? __high2half(khi) : __low2half(khi));
            ks[j][d]      = k0 * co - k1 * s;
            ks[j][d + 64] = k1 * co + k0 * s;
            vs[j][d]      = __half2float(u ? __high2half(vlo) : __low2half(vlo));
            vs[j][d + 64] = __half2float(u ? __high2half(vhi) : __low2half(vhi));
        }
    }
    // Q: NHEADS*32 threads handle 2 dims each
    for (int idx = tid; idx < NHEADS * 32; idx += 256) {
        int h = idx >> 5, dd = (idx & 31) * 2;
        const __half* qptr = base + h * HD;
        __half2 qlo = *reinterpret_cast<const __half2*>(qptr + dd);
        __half2 qhi = *reinterpret_cast<const __half2*>(qptr + 64 + dd);
        #pragma unroll
        for (int u = 0; u < 2; u++) {
            int d = dd + u;
            float s = sp[d], co = cp[d];
            float q0 = __half2float(u ? __high2half(qlo) : __low2half(qlo));
            float q1 = __half2float(u ? __high2half(qhi) : __low2half(qhi));
            qs[h][d]      = q0 * co - q1 * s;
            qs[h][d + 64] = q1 * co + q0 * s;
        }
    }
    __syncthreads();

    const int h = tid >> 3, j = tid & 7;
    float acc = 0.f;
    #pragma unroll 8
    for (int d = 0; d < HD; d++) acc += qs[h][d] * ks[j][d];
    float sc = acc / sqrtf(128.0f);

    float m = sc;
    m = fmaxf(m, __shfl_xor_sync(0xffffffffu, m, 1));
    m = fmaxf(m, __shfl_xor_sync(0xffffffffu, m, 2));
    m = fmaxf(m, __shfl_xor_sync(0xffffffffu, m, 4));
    float e = expf(sc - m);
    float z = e;
    z += __shfl_xor_sync(0xffffffffu, z, 1);
    z += __shfl_xor_sync(0xffffffffu, z, 2);
    z += __shfl_xor_sync(0xffffffffu, z, 4);
    ps[h][j] = e / z;
    __syncthreads();

    // out: 2 elems per thread per iter, __half2 stores
    #pragma unroll
    for (int it = 0; it < 8; it++) {
        int idx2 = (tid + it * 256) * 2;       // even element index
        int hh = idx2 >> 7, d = idx2 & 127;
        float a0 = 0.f, a1 = 0.f;
        #pragma unroll
        for (int jj = 0; jj < NKV; jj++) {
            a0 += ps[hh][jj] * vs[jj][d];
            a1 += ps[hh][jj] * vs[jj][d + 1];
        }
        *reinterpret_cast<__half2*>(g_Yh + (size_t)tok * HSZ + idx2) =
            __floats2half2_rn(a0, a1);
    }
}

// ---------------- launch ----------------------------------------------------
extern "C" void kernel_launch(void* const* d_in, const int* in_sizes, int n_in,
                              void* d_out, int out_size)
{
    const float* hs = (const float*)d_in[0];
    const float* Wq = (const float*)d_in[1];
    const float* Wk = (const float*)d_in[2];
    const float* Wv = (const float*)d_in[3];
    const float* Wo = (const float*)d_in[4];
    float* out = (float*)d_out;

    __half *xh, *wqkvh, *woh, *qkvh, *yh;
    cudaGetSymbolAddress((void**)&xh,    g_Xh);
    cudaGetSymbolAddress((void**)&wqkvh, g_Wqkvh);
    cudaGetSymbolAddress((void**)&woh,   g_Woh);
    cudaGetSymbolAddress((void**)&qkvh,  g_QKVh);
    cudaGetSymbolAddress((void**)&yh,    g_Yh);

    cudaFuncSetAttribute(gemm_f16<true>,  cudaFuncAttributeMaxDynamicSharedMemorySize, GEMM_DYN);
    cudaFuncSetAttribute(gemm_f16<false>, cudaFuncAttributeMaxDynamicSharedMemorySize, GEMM_DYN);

    // prep (fused, emb computed in-block)
    prep_kernel<<<PREP_BLOCKS, 256>>>(hs, Wq, Wk, Wv, Wo);

    // fused QKV projection: [8192,4096] @ [4096,6144] -> fp16 (persistent grid)
    gemm_f16<true><<<GEMM_GRID, NTHR, GEMM_DYN>>>(xh, wqkvh, qkvh, NQKV);

    attn_kernel<<<MTOT, 256>>>();

    // output projection: [8192,4096] @ [4096,4096] -> fp32 (persistent grid)
    gemm_f16<false><<<GEMM_GRID, NTHR, GEMM_DYN>>>(yh, woh, out, HSZ);
}

// round 15
// speedup vs baseline: 1.1282x; 1.1282x over previous
#include <cuda_runtime.h>
#include <cuda_fp16.h>
#include <cstdint>
#include <math.h>

// Problem constants
#define HSZ    4096
#define NHEADS 32
#define NKV    8
#define HD     128
#define SEQ    4096
#define BATCH  2
#define MTOT   (BATCH * SEQ)   // 8192
#define KD     4096
#define NQKV   6144            // 4096 + 1024 + 1024

// ---------------- scratch (device globals) ---------------------------------
__device__ __half g_Xh[(size_t)MTOT * HSZ];     // fp16 hidden_states
__device__ __half g_Wqkvh[(size_t)KD * NQKV];   // packed [K][6144] fp16
__device__ __half g_Woh[(size_t)KD * HSZ];      // Wo fp16 [K][N]
__device__ __half g_QKVh[(size_t)MTOT * NQKV];  // q|k|v per token (fp16)
__device__ __half g_Yh[(size_t)MTOT * HSZ];     // attn out fp16
__device__ float  g_sin[SEQ * 64];
__device__ float  g_cos[SEQ * 64];

// ---------------- helpers ---------------------------------------------------
__device__ __forceinline__ uint32_t s2u(const void* p) {
    uint32_t a;
    asm("{ .reg .u64 t; cvta.to.shared.u64 t, %1; cvt.u32.u64 %0, t; }"
        : "=r"(a) : "l"(p));
    return a;
}
__device__ __forceinline__ void cpa16(uint32_t dst, const void* src) {
    asm volatile("cp.async.cg.shared.global [%0], [%1], 16;" :: "r"(dst), "l"(src) : "memory");
}
__device__ __forceinline__ void cpa_commit() {
    asm volatile("cp.async.commit_group;" ::: "memory");
}
template<int N_>
__device__ __forceinline__ void cpa_wait() {
    asm volatile("cp.async.wait_group %0;" :: "n"(N_) : "memory");
}
__device__ __forceinline__ void ldmA(uint32_t r[4], uint32_t addr) {
    asm volatile("ldmatrix.sync.aligned.m8n8.x4.shared.b16 {%0,%1,%2,%3}, [%4];"
                 : "=r"(r[0]), "=r"(r[1]), "=r"(r[2]), "=r"(r[3]) : "r"(addr));
}
__device__ __forceinline__ void ldmB4(uint32_t r[4], uint32_t addr) {
    asm volatile("ldmatrix.sync.aligned.m8n8.x4.trans.shared.b16 {%0,%1,%2,%3}, [%4];"
                 : "=r"(r[0]), "=r"(r[1]), "=r"(r[2]), "=r"(r[3]) : "r"(addr));
}
__device__ __forceinline__ void mma16816(float c[4], const uint32_t a[4],
                                         uint32_t b0, uint32_t b1) {
    asm("mma.sync.aligned.m16n8k16.row.col.f32.f16.f16.f32 "
        "{%0,%1,%2,%3}, {%4,%5,%6,%7}, {%8,%9}, {%0,%1,%2,%3};"
        : "+f"(c[0]), "+f"(c[1]), "+f"(c[2]), "+f"(c[3])
        : "r"(a[0]), "r"(a[1]), "r"(a[2]), "r"(a[3]), "r"(b0), "r"(b1));
}

// ---------------- RoPE helpers ----------------------------------------------
// accurate sincos of a double argument (|x| < 2^26), explicit DFMA only
__device__ __forceinline__ void dsincos(double x, float* so, float* co) {
    double n = rint(x * 0.63661977236758138);       // x * 2/pi
    long long qi = (long long)n;
    double r = fma(n, -1.5707963267948966, x);      // pi/2 hi
    r = fma(n, -6.123233995736766e-17, r);          // pi/2 lo
    double r2 = r * r;
    double p = fma(r2, 2.7557319223985893e-06, -1.9841269841269841e-04);
    p = fma(r2, p, 8.3333333333333332e-03);
    p = fma(r2, p, -1.6666666666666666e-01);
    double sinr = fma(r * r2, p, r);
    double q = fma(r2, -2.7557319223985888e-07, 2.4801587301587302e-05);
    q = fma(r2, q, -1.3888888888888889e-03);
    q = fma(r2, q, 4.1666666666666666e-02);
    q = fma(r2, q, -0.5);
    double cosr = fma(r2, q, 1.0);
    switch ((int)(qi & 3)) {
        case 0: *so = (float)sinr;  *co = (float)cosr;  break;
        case 1: *so = (float)cosr;  *co = (float)-sinr; break;
        case 2: *so = (float)-sinr; *co = (float)-cosr; break;
        default:*so = (float)-cosr; *co = (float)sinr;  break;
    }
}

// ---------------- fused prep: f2h(hs) | f2h(Wo) | pack_qkv | rope -----------
// block ranges: [0,1024) hs->Xh, [1024,1536) Wo->Woh, [1536,2304) pack, [2304,2560) rope
#define PREP_BLOCKS 2560

__device__ __forceinline__ void f2h_range(const float* __restrict__ src,
                                          __half* __restrict__ dst,
                                          size_t n4, int blk, int nblk) {
    size_t stride = (size_t)nblk * 256;
    for (size_t i = (size_t)blk * 256 + threadIdx.x; i < n4; i += stride) {
        float4 v = reinterpret_cast<const float4*>(src)[i];
        __half2 h0 = __floats2half2_rn(v.x, v.y);
        __half2 h1 = __floats2half2_rn(v.z, v.w);
        uint2 u;
        u.x = *reinterpret_cast<uint32_t*>(&h0);
        u.y = *reinterpret_cast<uint32_t*>(&h1);
        *reinterpret_cast<uint2*>(dst + i * 4) = u;
    }
}

__global__ __launch_bounds__(256)
void prep_kernel(const float* __restrict__ hs, const float* __restrict__ Wq,
                 const float* __restrict__ Wk, const float* __restrict__ Wv,
                 const float* __restrict__ Wo)
{
    const int b = blockIdx.x;
    if (b < 1024) {
        f2h_range(hs, g_Xh, (size_t)MTOT * HSZ / 4, b, 1024);
    } else if (b < 1536) {
        f2h_range(Wo, g_Woh, (size_t)KD * HSZ / 4, b - 1024, 512);
    } else if (b < 2304) {
        const int blk = b - 1536;
        const size_t total = (size_t)KD * NQKV / 4;
        size_t stride = (size_t)768 * 256;
        for (size_t i = (size_t)blk * 256 + threadIdx.x; i < total; i += stride) {
            int row = (int)(i / (NQKV / 4));
            int col = (int)(i % (NQKV / 4)) * 4;
            float4 v;
            if (col < 4096)
                v = *reinterpret_cast<const float4*>(Wq + (size_t)row * 4096 + col);
            else if (col < 5120)
                v = *reinterpret_cast<const float4*>(Wk + (size_t)row * 1024 + (col - 4096));
            else
                v = *reinterpret_cast<const float4*>(Wv + (size_t)row * 1024 + (col - 5120));
            __half2 h0 = __floats2half2_rn(v.x, v.y);
            __half2 h1 = __floats2half2_rn(v.z, v.w);
            uint2 u;
            u.x = *reinterpret_cast<uint32_t*>(&h0);
            u.y = *reinterpret_cast<uint32_t*>(&h1);
            *reinterpret_cast<uint2*>(g_Wqkvh + (size_t)row * NQKV + col) = u;
        }
    } else {
        // rope: compute emb locally (bit-identical double pow), then table slice
        __shared__ float emb_s[64];
        if (threadIdx.x < 64) {
            int d  = threadIdx.x;
            int k2 = d & ~1;
            float e = (float)k2 / 64.0f;
            emb_s[d] = (float)pow(10000.0, (double)e);
        }
        __syncthreads();
        const int blk = b - 2304;                      // 0..255
        int idx = blk * 1024 + threadIdx.x;            // covers SEQ*64 via 4 steps
        #pragma unroll
        for (int t = 0; t < 4; t++, idx += 256) {
            int pos = idx >> 6, d = idx & 63;
            float emb  = emb_s[d];
            float freq = (float)pos * emb;             // single fp32 rounding, like jax
            float s, c;
            dsincos((double)freq, &s, &c);
            g_sin[idx] = s;
            g_cos[idx] = c;
        }
    }
}

// ---------------- pipelined FP16 GEMM (fp32 accumulate) ----------------------
// C[M,N] = A[M,K] @ B[K,N]. fp16 in. K = 4096.
// CTA tile 128x256, 512 threads (16 warps, 2x8), warp tile 64x32, 3 stages.
// K-loop unrolled by 3 so ring-slot smem bases are compile-time constants.
#define BM 128
#define BN 256
#define BK 64
#define NTHR 512
#define STAGES 3
#define PA 72                          // A smem row pitch (halves)
#define PB 264                         // B smem row pitch (halves)
#define A_HALVES (BM * PA)             // 9216
#define B_HALVES (BK * PB)             // 16896
#define STAGE_HALVES (A_HALVES + B_HALVES)
#define STAGE_BYTES (STAGE_HALVES * 2)       // 52224
#define GEMM_DYN (STAGES * STAGE_BYTES)      // 156672
#define NT (KD / BK)                   // 64

template<bool HALF_OUT>
__global__ __launch_bounds__(NTHR, 1)
void gemm_f16(const __half* __restrict__ A, const __half* __restrict__ B,
              void* __restrict__ Cv, int N)
{
    extern __shared__ __half dynh[];
    const uint32_t sbase = s2u(dynh);

    const int tid  = threadIdx.x;
    const int lane = tid & 31, warp = tid >> 5;
    const int warpM = warp & 1;        // 64-row slab
    const int warpN = warp >> 1;       // 0..7 -> 32-col slab
    const int g  = lane >> 2;
    const int tg = lane & 3;

    // L2-friendly mapping: groups of 8 m-tiles across all n-tiles
    const int n_tiles = N / BN;
    const int per = 8 * n_tiles;
    const int gblk = blockIdx.x / per, rr0 = blockIdx.x % per;
    const int mt = gblk * 8 + (rr0 & 7);
    const int nt = rr0 >> 3;
    const int rowBase = mt * BM;
    const int colBase = nt * BN;

    const __half* Ag = A + (size_t)rowBase * KD;

    float c[4][4][4];
    #pragma unroll
    for (int m2 = 0; m2 < 4; m2++)
        #pragma unroll
        for (int n2 = 0; n2 < 4; n2++)
            #pragma unroll
            for (int i = 0; i < 4; i++) c[m2][n2][i] = 0.f;

    // ---- load issuer: K-tile kt -> stage slot s (compile-time s at call sites)
    auto issue = [&](int kt, int s) {
        const uint32_t sa = sbase + s * STAGE_BYTES;
        const uint32_t sb = sa + A_HALVES * 2;
        #pragma unroll
        for (int i = 0; i < 2; i++) {          // A: 128 rows x 128B = 1024 chunks
            int ch = tid + i * NTHR;
            int r = ch >> 3, c8 = ch & 7;
            cpa16(sa + (r * PA + c8 * 8) * 2,
                  Ag + (size_t)r * KD + kt * BK + c8 * 8);
        }
        #pragma unroll
        for (int i = 0; i < 4; i++) {          // B: 64 rows x 512B = 2048 chunks
            int ch = tid + i * NTHR;
            int r = ch >> 5, c8 = ch & 31;
            cpa16(sb + (r * PB + c8 * 8) * 2,
                  B + (size_t)(kt * BK + r) * N + colBase + c8 * 8);
        }
    };

    issue(0, 0); cpa_commit();
    issue(1, 1); cpa_commit();

    // ldmatrix per-lane byte offsets
    const uint32_t a_off = ((warpM * 64 + (lane & 15)) * PA + (lane >> 4) * 8) * 2;
    const uint32_t b_off = ((lane & 15) * PB + warpN * 32 + (lane >> 4) * 8) * 2;

    // one K-iteration with compile-time ring slot
    auto kstep = [&](int kt, const int slot) {
        cpa_wait<STAGES - 2>();
        __syncthreads();

        const int gn = kt + STAGES - 1;
        const int sn = (slot + STAGES - 1) % STAGES;   // folds: slot literal
        if (gn < NT) issue(gn, sn);
        cpa_commit();

        const uint32_t sa = sbase + slot * STAGE_BYTES;
        const uint32_t sb = sa + A_HALVES * 2;

        #pragma unroll
        for (int ks = 0; ks < 4; ks++) {       // 4 x k16
            uint32_t af[4][4], bf[2][4];
            #pragma unroll
            for (int m2 = 0; m2 < 4; m2++)
                ldmA(af[m2], sa + a_off + (m2 * 16 * PA + ks * 16) * 2);
            #pragma unroll
            for (int n4 = 0; n4 < 2; n4++)
                ldmB4(bf[n4], sb + b_off + (ks * 16 * PB + n4 * 16) * 2);
            #pragma unroll
            for (int m2 = 0; m2 < 4; m2++)
                #pragma unroll
                for (int n4 = 0; n4 < 2; n4++) {
                    mma16816(c[m2][n4 * 2    ], af[m2], bf[n4][0], bf[n4][1]);
                    mma16816(c[m2][n4 * 2 + 1], af[m2], bf[n4][2], bf[n4][3]);
                }
        }
    };

    // NT = 64 = 3*21 + 1: 21 triples with literal slots, then remainder (slot 0)
    for (int kt = 0; kt < NT - 1; kt += 3) {
        kstep(kt,     0);
        kstep(kt + 1, 1);
        kstep(kt + 2, 2);
    }
    kstep(NT - 1, 0);

    // epilogue
    #pragma unroll
    for (int m2 = 0; m2 < 4; m2++) {
        #pragma unroll
        for (int n2 = 0; n2 < 4; n2++) {
            int row = rowBase + warpM * 64 + m2 * 16 + g;
            int col = colBase + warpN * 32 + n2 * 8 + tg * 2;
            if (HALF_OUT) {
                __half* C = (__half*)Cv;
                __half2 v01 = __floats2half2_rn(c[m2][n2][0], c[m2][n2][1]);
                __half2 v23 = __floats2half2_rn(c[m2][n2][2], c[m2][n2][3]);
                *reinterpret_cast<__half2*>(C + (size_t)row * N + col)       = v01;
                *reinterpret_cast<__half2*>(C + (size_t)(row + 8) * N + col) = v23;
            } else {
                float* C = (float*)Cv;
                float2 v01 = make_float2(c[m2][n2][0], c[m2][n2][1]);
                float2 v23 = make_float2(c[m2][n2][2], c[m2][n2][3]);
                *reinterpret_cast<float2*>(C + (size_t)row * N + col)       = v01;
                *reinterpret_cast<float2*>(C + (size_t)(row + 8) * N + col) = v23;
            }
        }
    }
}

// ---------------- RoPE + per-token GQA attention (R10 exact) -----------------
__global__ __launch_bounds__(256)
void attn_kernel()
{
    const int tok = blockIdx.x;
    const int pos = tok & (SEQ - 1);
    const int tid = threadIdx.x;

    __shared__ float qs[NHEADS][HD + 4];
    __shared__ float ks[NKV][HD + 4];
    __shared__ float vs[NKV][HD + 4];
    __shared__ float ps[NHEADS][NKV];

    const float* sp = g_sin + pos * 64;
    const float* cp = g_cos + pos * 64;
    const __half* base = g_QKVh + (size_t)tok * NQKV;

    // K/V: NKV*32 threads handle 2 dims each via __half2
    for (int idx = tid; idx < NKV * 32; idx += 256) {
        int j = idx >> 5, dd = (idx & 31) * 2;
        const __half* kptr = base + 4096 + j * HD;
        const __half* vptr = base + 5120 + j * HD;
        __half2 klo = *reinterpret_cast<const __half2*>(kptr + dd);
        __half2 khi = *reinterpret_cast<const __half2*>(kptr + 64 + dd);
        __half2 vlo = *reinterpret_cast<const __half2*>(vptr + dd);
        __half2 vhi = *reinterpret_cast<const __half2*>(vptr + 64 + dd);
        #pragma unroll
        for (int u = 0; u < 2; u++) {
            int d = dd + u;
            float s = sp[d], co = cp[d];
            float k0 = __half2float(u ? __high2half(klo) : __low2half(klo));
            float k1 = __half2float(u ? __high2half(khi) : __low2half(khi));
            ks[j][d]      = k0 * co - k1 * s;
            ks[j][d + 64] = k1 * co + k0 * s;
            vs[j][d]      = __half2float(u ? __high2half(vlo) : __low2half(vlo));
            vs[j][d + 64] = __half2float(u ? __high2half(vhi) : __low2half(vhi));
        }
    }
    // Q: NHEADS*32 threads handle 2 dims each
    for (int idx = tid; idx < NHEADS * 32; idx += 256) {
        int h = idx >> 5, dd = (idx & 31) * 2;
        const __half* qptr = base + h * HD;
        __half2 qlo = *reinterpret_cast<const __half2*>(qptr + dd);
        __half2 qhi = *reinterpret_cast<const __half2*>(qptr + 64 + dd);
        #pragma unroll
        for (int u = 0; u < 2; u++) {
            int d = dd + u;
            float s = sp[d], co = cp[d];
            float q0 = __half2float(u ? __high2half(qlo) : __low2half(qlo));
            float q1 = __half2float(u ? __high2half(qhi) : __low2half(qhi));
            qs[h][d]      = q0 * co - q1 * s;
            qs[h][d + 64] = q1 * co + q0 * s;
        }
    }
    __syncthreads();

    const int h = tid >> 3, j = tid & 7;
    float acc = 0.f;
    #pragma unroll 8
    for (int d = 0; d < HD; d++) acc += qs[h][d] * ks[j][d];
    float sc = acc / sqrtf(128.0f);

    float m = sc;
    m = fmaxf(m, __shfl_xor_sync(0xffffffffu, m, 1));
    m = fmaxf(m, __shfl_xor_sync(0xffffffffu, m, 2));
    m = fmaxf(m, __shfl_xor_sync(0xffffffffu, m, 4));
    float e = expf(sc - m);
    float z = e;
    z += __shfl_xor_sync(0xffffffffu, z, 1);
    z += __shfl_xor_sync(0xffffffffu, z, 2);
    z += __shfl_xor_sync(0xffffffffu, z, 4);
    ps[h][j] = e / z;
    __syncthreads();

    // out: 2 elems per thread per iter, __half2 stores
    #pragma unroll
    for (int it = 0; it < 8; it++) {
        int idx2 = (tid + it * 256) * 2;       // even element index
        int hh = idx2 >> 7, d = idx2 & 127;
        float a0 = 0.f, a1 = 0.f;
        #pragma unroll
        for (int jj = 0; jj < NKV; jj++) {
            a0 += ps[hh][jj] * vs[jj][d];
            a1 += ps[hh][jj] * vs[jj][d + 1];
        }
        *reinterpret_cast<__half2*>(g_Yh + (size_t)tok * HSZ + idx2) =
            __floats2half2_rn(a0, a1);
    }
}

// ---------------- launch ----------------------------------------------------
extern "C" void kernel_launch(void* const* d_in, const int* in_sizes, int n_in,
                              void* d_out, int out_size)
{
    const float* hs = (const float*)d_in[0];
    const float* Wq = (const float*)d_in[1];
    const float* Wk = (const float*)d_in[2];
    const float* Wv = (const float*)d_in[3];
    const float* Wo = (const float*)d_in[4];
    float* out = (float*)d_out;

    __half *xh, *wqkvh, *woh, *qkvh, *yh;
    cudaGetSymbolAddress((void**)&xh,    g_Xh);
    cudaGetSymbolAddress((void**)&wqkvh, g_Wqkvh);
    cudaGetSymbolAddress((void**)&woh,   g_Woh);
    cudaGetSymbolAddress((void**)&qkvh,  g_QKVh);
    cudaGetSymbolAddress((void**)&yh,    g_Yh);

    cudaFuncSetAttribute(gemm_f16<true>,  cudaFuncAttributeMaxDynamicSharedMemorySize, GEMM_DYN);
    cudaFuncSetAttribute(gemm_f16<false>, cudaFuncAttributeMaxDynamicSharedMemorySize, GEMM_DYN);

    // prep (fused, emb computed in-block)
    prep_kernel<<<PREP_BLOCKS, 256>>>(hs, Wq, Wk, Wv, Wo);

    // fused QKV projection: [8192,4096] @ [4096,6144] -> fp16
    gemm_f16<true><<<(MTOT / BM) * (NQKV / BN), NTHR, GEMM_DYN>>>(xh, wqkvh, qkvh, NQKV);

    attn_kernel<<<MTOT, 256>>>();

    // output projection: [8192,4096] @ [4096,4096] -> fp32 (d_out)
    gemm_f16<false><<<(MTOT / BM) * (HSZ / BN), NTHR, GEMM_DYN>>>(yh, woh, out, HSZ);
}

// round 16
// speedup vs baseline: 1.1849x; 1.0503x over previous
#include <cuda_runtime.h>
#include <cuda_fp16.h>
#include <cstdint>
#include <math.h>

// Problem constants
#define HSZ    4096
#define NHEADS 32
#define NKV    8
#define HD     128
#define SEQ    4096
#define BATCH  2
#define MTOT   (BATCH * SEQ)   // 8192
#define KD     4096
#define NQKV   6144            // 4096 + 1024 + 1024

// ---------------- scratch (device globals) ---------------------------------
__device__ __half g_Xh[(size_t)MTOT * HSZ];     // fp16 hidden_states
__device__ __half g_Wqkvh[(size_t)KD * NQKV];   // packed [K][6144] fp16
__device__ __half g_Woh[(size_t)KD * HSZ];      // Wo fp16 [K][N]
__device__ __half g_QKVh[(size_t)MTOT * NQKV];  // q|k|v per token (fp16)
__device__ __half g_Yh[(size_t)MTOT * HSZ];     // attn out fp16
__device__ float  g_sin[SEQ * 64];
__device__ float  g_cos[SEQ * 64];

// ---------------- helpers ---------------------------------------------------
__device__ __forceinline__ uint32_t s2u(const void* p) {
    uint32_t a;
    asm("{ .reg .u64 t; cvta.to.shared.u64 t, %1; cvt.u32.u64 %0, t; }"
        : "=r"(a) : "l"(p));
    return a;
}
__device__ __forceinline__ void cpa16(uint32_t dst, const void* src) {
    asm volatile("cp.async.cg.shared.global [%0], [%1], 16;" :: "r"(dst), "l"(src) : "memory");
}
__device__ __forceinline__ void cpa_commit() {
    asm volatile("cp.async.commit_group;" ::: "memory");
}
template<int N_>
__device__ __forceinline__ void cpa_wait() {
    asm volatile("cp.async.wait_group %0;" :: "n"(N_) : "memory");
}
__device__ __forceinline__ void ldmA(uint32_t r[4], uint32_t addr) {
    asm volatile("ldmatrix.sync.aligned.m8n8.x4.shared.b16 {%0,%1,%2,%3}, [%4];"
                 : "=r"(r[0]), "=r"(r[1]), "=r"(r[2]), "=r"(r[3]) : "r"(addr));
}
__device__ __forceinline__ void ldmB4(uint32_t r[4], uint32_t addr) {
    asm volatile("ldmatrix.sync.aligned.m8n8.x4.trans.shared.b16 {%0,%1,%2,%3}, [%4];"
                 : "=r"(r[0]), "=r"(r[1]), "=r"(r[2]), "=r"(r[3]) : "r"(addr));
}
__device__ __forceinline__ void mma16816(float c[4], const uint32_t a[4],
                                         uint32_t b0, uint32_t b1) {
    asm("mma.sync.aligned.m16n8k16.row.col.f32.f16.f16.f32 "
        "{%0,%1,%2,%3}, {%4,%5,%6,%7}, {%8,%9}, {%0,%1,%2,%3};"
        : "+f"(c[0]), "+f"(c[1]), "+f"(c[2]), "+f"(c[3])
        : "r"(a[0]), "r"(a[1]), "r"(a[2]), "r"(a[3]), "r"(b0), "r"(b1));
}

// ---------------- RoPE helpers ----------------------------------------------
// accurate sincos of a double argument (|x| < 2^26), explicit DFMA only
__device__ __forceinline__ void dsincos(double x, float* so, float* co) {
    double n = rint(x * 0.63661977236758138);       // x * 2/pi
    long long qi = (long long)n;
    double r = fma(n, -1.5707963267948966, x);      // pi/2 hi
    r = fma(n, -6.123233995736766e-17, r);          // pi/2 lo
    double r2 = r * r;
    double p = fma(r2, 2.7557319223985893e-06, -1.9841269841269841e-04);
    p = fma(r2, p, 8.3333333333333332e-03);
    p = fma(r2, p, -1.6666666666666666e-01);
    double sinr = fma(r * r2, p, r);
    double q = fma(r2, -2.7557319223985888e-07, 2.4801587301587302e-05);
    q = fma(r2, q, -1.3888888888888889e-03);
    q = fma(r2, q, 4.1666666666666666e-02);
    q = fma(r2, q, -0.5);
    double cosr = fma(r2, q, 1.0);
    switch ((int)(qi & 3)) {
        case 0: *so = (float)sinr;  *co = (float)cosr;  break;
        case 1: *so = (float)cosr;  *co = (float)-sinr; break;
        case 2: *so = (float)-sinr; *co = (float)-cosr; break;
        default:*so = (float)-cosr; *co = (float)sinr;  break;
    }
}

// ---------------- fused prep: f2h(hs) | f2h(Wo) | pack_qkv | rope -----------
// block ranges: [0,1024) hs->Xh, [1024,1536) Wo->Woh, [1536,2304) pack, [2304,2560) rope
#define PREP_BLOCKS 2560

__device__ __forceinline__ void f2h_range(const float* __restrict__ src,
                                          __half* __restrict__ dst,
                                          size_t n4, int blk, int nblk) {
    size_t stride = (size_t)nblk * 256;
    for (size_t i = (size_t)blk * 256 + threadIdx.x; i < n4; i += stride) {
        float4 v = reinterpret_cast<const float4*>(src)[i];
        __half2 h0 = __floats2half2_rn(v.x, v.y);
        __half2 h1 = __floats2half2_rn(v.z, v.w);
        uint2 u;
        u.x = *reinterpret_cast<uint32_t*>(&h0);
        u.y = *reinterpret_cast<uint32_t*>(&h1);
        *reinterpret_cast<uint2*>(dst + i * 4) = u;
    }
}

__global__ __launch_bounds__(256)
void prep_kernel(const float* __restrict__ hs, const float* __restrict__ Wq,
                 const float* __restrict__ Wk, const float* __restrict__ Wv,
                 const float* __restrict__ Wo)
{
    const int b = blockIdx.x;
    if (b < 1024) {
        f2h_range(hs, g_Xh, (size_t)MTOT * HSZ / 4, b, 1024);
    } else if (b < 1536) {
        f2h_range(Wo, g_Woh, (size_t)KD * HSZ / 4, b - 1024, 512);
    } else if (b < 2304) {
        const int blk = b - 1536;
        const size_t total = (size_t)KD * NQKV / 4;
        size_t stride = (size_t)768 * 256;
        for (size_t i = (size_t)blk * 256 + threadIdx.x; i < total; i += stride) {
            int row = (int)(i / (NQKV / 4));
            int col = (int)(i % (NQKV / 4)) * 4;
            float4 v;
            if (col < 4096)
                v = *reinterpret_cast<const float4*>(Wq + (size_t)row * 4096 + col);
            else if (col < 5120)
                v = *reinterpret_cast<const float4*>(Wk + (size_t)row * 1024 + (col - 4096));
            else
                v = *reinterpret_cast<const float4*>(Wv + (size_t)row * 1024 + (col - 5120));
            __half2 h0 = __floats2half2_rn(v.x, v.y);
            __half2 h1 = __floats2half2_rn(v.z, v.w);
            uint2 u;
            u.x = *reinterpret_cast<uint32_t*>(&h0);
            u.y = *reinterpret_cast<uint32_t*>(&h1);
            *reinterpret_cast<uint2*>(g_Wqkvh + (size_t)row * NQKV + col) = u;
        }
    } else {
        // rope: compute emb locally (bit-identical double pow), then table slice
        __shared__ float emb_s[64];
        if (threadIdx.x < 64) {
            int d  = threadIdx.x;
            int k2 = d & ~1;
            float e = (float)k2 / 64.0f;
            emb_s[d] = (float)pow(10000.0, (double)e);
        }
        __syncthreads();
        const int blk = b - 2304;                      // 0..255
        int idx = blk * 1024 + threadIdx.x;            // covers SEQ*64 via 4 steps
        #pragma unroll
        for (int t = 0; t < 4; t++, idx += 256) {
            int pos = idx >> 6, d = idx & 63;
            float emb  = emb_s[d];
            float freq = (float)pos * emb;             // single fp32 rounding, like jax
            float s, c;
            dsincos((double)freq, &s, &c);
            g_sin[idx] = s;
            g_cos[idx] = c;
        }
    }
}

// ---------------- pipelined FP16 GEMM (fp32 accumulate) ----------------------
// C[M,N] = A[M,K] @ B[K,N]. fp16 in. K = 4096.
// CTA tile 128x256, 512 threads (16 warps, 2x8), warp tile 64x32, 3 stages.
// K-loop: 20 branch-free triples (literal slots) + explicit peeled tail.
#define BM 128
#define BN 256
#define BK 64
#define NTHR 512
#define STAGES 3
#define PA 72                          // A smem row pitch (halves)
#define PB 264                         // B smem row pitch (halves)
#define A_HALVES (BM * PA)             // 9216
#define B_HALVES (BK * PB)             // 16896
#define STAGE_HALVES (A_HALVES + B_HALVES)
#define STAGE_BYTES (STAGE_HALVES * 2)       // 52224
#define GEMM_DYN (STAGES * STAGE_BYTES)      // 156672
#define NT (KD / BK)                   // 64

template<bool HALF_OUT>
__global__ __launch_bounds__(NTHR, 1)
void gemm_f16(const __half* __restrict__ A, const __half* __restrict__ B,
              void* __restrict__ Cv, int N)
{
    extern __shared__ __half dynh[];
    const uint32_t sbase = s2u(dynh);

    const int tid  = threadIdx.x;
    const int lane = tid & 31, warp = tid >> 5;
    const int warpM = warp & 1;        // 64-row slab
    const int warpN = warp >> 1;       // 0..7 -> 32-col slab
    const int g  = lane >> 2;
    const int tg = lane & 3;

    // L2-friendly mapping: groups of 8 m-tiles across all n-tiles
    const int n_tiles = N / BN;
    const int per = 8 * n_tiles;
    const int gblk = blockIdx.x / per, rr0 = blockIdx.x % per;
    const int mt = gblk * 8 + (rr0 & 7);
    const int nt = rr0 >> 3;
    const int rowBase = mt * BM;
    const int colBase = nt * BN;

    const __half* Ag = A + (size_t)rowBase * KD;

    float c[4][4][4];
    #pragma unroll
    for (int m2 = 0; m2 < 4; m2++)
        #pragma unroll
        for (int n2 = 0; n2 < 4; n2++)
            #pragma unroll
            for (int i = 0; i < 4; i++) c[m2][n2][i] = 0.f;

    // ---- load issuer: K-tile kt -> stage slot s (literal s at call sites)
    auto issue = [&](int kt, int s) {
        const uint32_t sa = sbase + s * STAGE_BYTES;
        const uint32_t sb = sa + A_HALVES * 2;
        #pragma unroll
        for (int i = 0; i < 2; i++) {          // A: 128 rows x 128B = 1024 chunks
            int ch = tid + i * NTHR;
            int r = ch >> 3, c8 = ch & 7;
            cpa16(sa + (r * PA + c8 * 8) * 2,
                  Ag + (size_t)r * KD + kt * BK + c8 * 8);
        }
        #pragma unroll
        for (int i = 0; i < 4; i++) {          // B: 64 rows x 512B = 2048 chunks
            int ch = tid + i * NTHR;
            int r = ch >> 5, c8 = ch & 31;
            cpa16(sb + (r * PB + c8 * 8) * 2,
                  B + (size_t)(kt * BK + r) * N + colBase + c8 * 8);
        }
    };

    issue(0, 0); cpa_commit();
    issue(1, 1); cpa_commit();

    // ldmatrix per-lane byte offsets
    const uint32_t a_off = ((warpM * 64 + (lane & 15)) * PA + (lane >> 4) * 8) * 2;
    const uint32_t b_off = ((lane & 15) * PB + warpN * 32 + (lane >> 4) * 8) * 2;

    // fragment-load + mma for one K-tile resident at (sa, sb)
    auto compute = [&](const uint32_t sa, const uint32_t sb) {
        #pragma unroll
        for (int ks = 0; ks < 4; ks++) {       // 4 x k16
            uint32_t af[4][4], bf[2][4];
            #pragma unroll
            for (int m2 = 0; m2 < 4; m2++)
                ldmA(af[m2], sa + a_off + (m2 * 16 * PA + ks * 16) * 2);
            #pragma unroll
            for (int n4 = 0; n4 < 2; n4++)
                ldmB4(bf[n4], sb + b_off + (ks * 16 * PB + n4 * 16) * 2);
            #pragma unroll
            for (int m2 = 0; m2 < 4; m2++)
                #pragma unroll
                for (int n4 = 0; n4 < 2; n4++) {
                    mma16816(c[m2][n4 * 2    ], af[m2], bf[n4][0], bf[n4][1]);
                    mma16816(c[m2][n4 * 2 + 1], af[m2], bf[n4][2], bf[n4][3]);
                }
        }
    };

    const uint32_t sa0 = sbase;
    const uint32_t sa1 = sbase + STAGE_BYTES;
    const uint32_t sa2 = sbase + 2 * STAGE_BYTES;
    const uint32_t sboff = A_HALVES * 2;

    // main loop: kt 0..59, 20 branch-free triples with unconditional issue
    for (int kt = 0; kt < 60; kt += 3) {
        cpa_wait<1>(); __syncthreads();
        issue(kt + 2, 2); cpa_commit();
        compute(sa0, sa0 + sboff);

        cpa_wait<1>(); __syncthreads();
        issue(kt + 3, 0); cpa_commit();
        compute(sa1, sa1 + sboff);

        cpa_wait<1>(); __syncthreads();
        issue(kt + 4, 1); cpa_commit();
        compute(sa2, sa2 + sboff);
    }
    // kt = 60 (slot 0, issue 62 -> slot 2)
    cpa_wait<1>(); __syncthreads();
    issue(62, 2); cpa_commit();
    compute(sa0, sa0 + sboff);
    // kt = 61 (slot 1, issue 63 -> slot 0)
    cpa_wait<1>(); __syncthreads();
    issue(63, 0); cpa_commit();
    compute(sa1, sa1 + sboff);
    // kt = 62 (slot 2, no issue)
    cpa_wait<1>(); __syncthreads();
    compute(sa2, sa2 + sboff);
    // kt = 63 (slot 0, no issue; drain all)
    cpa_wait<0>(); __syncthreads();
    compute(sa0, sa0 + sboff);

    // epilogue
    #pragma unroll
    for (int m2 = 0; m2 < 4; m2++) {
        #pragma unroll
        for (int n2 = 0; n2 < 4; n2++) {
            int row = rowBase + warpM * 64 + m2 * 16 + g;
            int col = colBase + warpN * 32 + n2 * 8 + tg * 2;
            if (HALF_OUT) {
                __half* C = (__half*)Cv;
                __half2 v01 = __floats2half2_rn(c[m2][n2][0], c[m2][n2][1]);
                __half2 v23 = __floats2half2_rn(c[m2][n2][2], c[m2][n2][3]);
                *reinterpret_cast<__half2*>(C + (size_t)row * N + col)       = v01;
                *reinterpret_cast<__half2*>(C + (size_t)(row + 8) * N + col) = v23;
            } else {
                float* C = (float*)Cv;
                float2 v01 = make_float2(c[m2][n2][0], c[m2][n2][1]);
                float2 v23 = make_float2(c[m2][n2][2], c[m2][n2][3]);
                *reinterpret_cast<float2*>(C + (size_t)row * N + col)       = v01;
                *reinterpret_cast<float2*>(C + (size_t)(row + 8) * N + col) = v23;
            }
        }
    }
}

// ---------------- RoPE + per-token GQA attention -----------------------------
// Q/K staged as fp32 (RoPE'd); V staged as raw half2 bits (pass-through).
__global__ __launch_bounds__(256)
void attn_kernel()
{
    const int tok = blockIdx.x;
    const int pos = tok & (SEQ - 1);
    const int tid = threadIdx.x;

    __shared__ float    qs[NHEADS][HD + 4];
    __shared__ float    ks[NKV][HD + 4];
    __shared__ uint32_t vs2[NKV][64 + 4];    // half2 pairs; [0..31]=dims 0..63, [32..63]=64..127
    __shared__ float    ps[NHEADS][NKV];

    const float* sp = g_sin + pos * 64;
    const float* cp = g_cos + pos * 64;
    const __half* base = g_QKVh + (size_t)tok * NQKV;

    // K/V: NKV*32 threads handle 2 dims each
    for (int idx = tid; idx < NKV * 32; idx += 256) {
        int j = idx >> 5, dd = (idx & 31) * 2;
        const __half* kptr = base + 4096 + j * HD;
        const __half* vptr = base + 5120 + j * HD;
        __half2 klo = *reinterpret_cast<const __half2*>(kptr + dd);
        __half2 khi = *reinterpret_cast<const __half2*>(kptr + 64 + dd);
        uint32_t vlo = *reinterpret_cast<const uint32_t*>(vptr + dd);
        uint32_t vhi = *reinterpret_cast<const uint32_t*>(vptr + 64 + dd);
        vs2[j][dd >> 1]        = vlo;
        vs2[j][32 + (dd >> 1)] = vhi;
        #pragma unroll
        for (int u = 0; u < 2; u++) {
            int d = dd + u;
            float s = sp[d], co = cp[d];
            float k0 = __half2float(u ? __high2half(klo) : __low2half(klo));
            float k1 = __half2float(u ? __high2half(khi) : __low2half(khi));
            ks[j][d]      = k0 * co - k1 * s;
            ks[j][d + 64] = k1 * co + k0 * s;
        }
    }
    // Q: NHEADS*32 threads handle 2 dims each
    for (int idx = tid; idx < NHEADS * 32; idx += 256) {
        int h = idx >> 5, dd = (idx & 31) * 2;
        const __half* qptr = base + h * HD;
        __half2 qlo = *reinterpret_cast<const __half2*>(qptr + dd);
        __half2 qhi = *reinterpret_cast<const __half2*>(qptr + 64 + dd);
        #pragma unroll
        for (int u = 0; u < 2; u++) {
            int d = dd + u;
            float s = sp[d], co = cp[d];
            float q0 = __half2float(u ? __high2half(qlo) : __low2half(qlo));
            float q1 = __half2float(u ? __high2half(qhi) : __low2half(qhi));
            qs[h][d]      = q0 * co - q1 * s;
            qs[h][d + 64] = q1 * co + q0 * s;
        }
    }
    __syncthreads();

    const int h = tid >> 3, j = tid & 7;
    float acc = 0.f;
    #pragma unroll 8
    for (int d = 0; d < HD; d++) acc += qs[h][d] * ks[j][d];
    float sc = acc / sqrtf(128.0f);

    float m = sc;
    m = fmaxf(m, __shfl_xor_sync(0xffffffffu, m, 1));
    m = fmaxf(m, __shfl_xor_sync(0xffffffffu, m, 2));
    m = fmaxf(m, __shfl_xor_sync(0xffffffffu, m, 4));
    float e = expf(sc - m);
    float z = e;
    z += __shfl_xor_sync(0xffffffffu, z, 1);
    z += __shfl_xor_sync(0xffffffffu, z, 2);
    z += __shfl_xor_sync(0xffffffffu, z, 4);
    ps[h][j] = e / z;
    __syncthreads();

    // out: 2 elems per thread per iter; v via raw half2 (identical floats/order)
    #pragma unroll
    for (int it = 0; it < 8; it++) {
        int idx2 = (tid + it * 256) * 2;       // even element index
        int hh = idx2 >> 7, d = idx2 & 127;
        int d2 = d >> 1;
        float a0 = 0.f, a1 = 0.f;
        #pragma unroll
        for (int jj = 0; jj < NKV; jj++) {
            float p = ps[hh][jj];
            uint32_t vb = vs2[jj][d2];
            __half2 v = *reinterpret_cast<__half2*>(&vb);
            a0 += p * __half2float(__low2half(v));
            a1 += p * __half2float(__high2half(v));
        }
        *reinterpret_cast<__half2*>(g_Yh + (size_t)tok * HSZ + idx2) =
            __floats2half2_rn(a0, a1);
    }
}

// ---------------- launch ----------------------------------------------------
extern "C" void kernel_launch(void* const* d_in, const int* in_sizes, int n_in,
                              void* d_out, int out_size)
{
    const float* hs = (const float*)d_in[0];
    const float* Wq = (const float*)d_in[1];
    const float* Wk = (const float*)d_in[2];
    const float* Wv = (const float*)d_in[3];
    const float* Wo = (const float*)d_in[4];
    float* out = (float*)d_out;

    __half *xh, *wqkvh, *woh, *qkvh, *yh;
    cudaGetSymbolAddress((void**)&xh,    g_Xh);
    cudaGetSymbolAddress((void**)&wqkvh, g_Wqkvh);
    cudaGetSymbolAddress((void**)&woh,   g_Woh);
    cudaGetSymbolAddress((void**)&qkvh,  g_QKVh);
    cudaGetSymbolAddress((void**)&yh,    g_Yh);

    cudaFuncSetAttribute(gemm_f16<true>,  cudaFuncAttributeMaxDynamicSharedMemorySize, GEMM_DYN);
    cudaFuncSetAttribute(gemm_f16<false>, cudaFuncAttributeMaxDynamicSharedMemorySize, GEMM_DYN);

    // prep (fused, emb computed in-block)
    prep_kernel<<<PREP_BLOCKS, 256>>>(hs, Wq, Wk, Wv, Wo);

    // fused QKV projection: [8192,4096] @ [4096,6144] -> fp16
    gemm_f16<true><<<(MTOT / BM) * (NQKV / BN), NTHR, GEMM_DYN>>>(xh, wqkvh, qkvh, NQKV);

    attn_kernel<<<MTOT, 256>>>();

    // output projection: [8192,4096] @ [4096,4096] -> fp32 (d_out)
    gemm_f16<false><<<(MTOT / BM) * (HSZ / BN), NTHR, GEMM_DYN>>>(yh, woh, out, HSZ);
}

// round 17
// speedup vs baseline: 1.2420x; 1.0482x over previous
#include <cuda_runtime.h>
#include <cuda_fp16.h>
#include <cstdint>
#include <math.h>

// Problem constants
#define HSZ    4096
#define NHEADS 32
#define NKV    8
#define HD     128
#define SEQ    4096
#define BATCH  2
#define MTOT   (BATCH * SEQ)   // 8192
#define KD     4096
#define NQKV   6144            // 4096 + 1024 + 1024

// ---------------- scratch (device globals) ---------------------------------
__device__ __half g_Xh[(size_t)MTOT * HSZ];     // fp16 hidden_states
__device__ __half g_Wqkvh[(size_t)KD * NQKV];   // packed [K][6144] fp16
__device__ __half g_Woh[(size_t)KD * HSZ];      // Wo fp16 [K][N]
__device__ __half g_QKVh[(size_t)MTOT * NQKV];  // q|k|v per token (fp16)
__device__ __half g_Yh[(size_t)MTOT * HSZ];     // attn out fp16
__device__ float  g_sin[SEQ * 64];
__device__ float  g_cos[SEQ * 64];

// ---------------- helpers ---------------------------------------------------
__device__ __forceinline__ uint32_t s2u(const void* p) {
    uint32_t a;
    asm("{ .reg .u64 t; cvta.to.shared.u64 t, %1; cvt.u32.u64 %0, t; }"
        : "=r"(a) : "l"(p));
    return a;
}
__device__ __forceinline__ void cpa16(uint32_t dst, const void* src) {
    asm volatile("cp.async.cg.shared.global [%0], [%1], 16;" :: "r"(dst), "l"(src) : "memory");
}
__device__ __forceinline__ void cpa_commit() {
    asm volatile("cp.async.commit_group;" ::: "memory");
}
template<int N_>
__device__ __forceinline__ void cpa_wait() {
    asm volatile("cp.async.wait_group %0;" :: "n"(N_) : "memory");
}
__device__ __forceinline__ void ldmA(uint32_t r[4], uint32_t addr) {
    asm volatile("ldmatrix.sync.aligned.m8n8.x4.shared.b16 {%0,%1,%2,%3}, [%4];"
                 : "=r"(r[0]), "=r"(r[1]), "=r"(r[2]), "=r"(r[3]) : "r"(addr));
}
__device__ __forceinline__ void ldmB4(uint32_t r[4], uint32_t addr) {
    asm volatile("ldmatrix.sync.aligned.m8n8.x4.trans.shared.b16 {%0,%1,%2,%3}, [%4];"
                 : "=r"(r[0]), "=r"(r[1]), "=r"(r[2]), "=r"(r[3]) : "r"(addr));
}
__device__ __forceinline__ void mma16816(float c[4], const uint32_t a[4],
                                         uint32_t b0, uint32_t b1) {
    asm("mma.sync.aligned.m16n8k16.row.col.f32.f16.f16.f32 "
        "{%0,%1,%2,%3}, {%4,%5,%6,%7}, {%8,%9}, {%0,%1,%2,%3};"
        : "+f"(c[0]), "+f"(c[1]), "+f"(c[2]), "+f"(c[3])
        : "r"(a[0]), "r"(a[1]), "r"(a[2]), "r"(a[3]), "r"(b0), "r"(b1));
}

// ---------------- RoPE helpers ----------------------------------------------
// accurate sincos of a double argument (|x| < 2^26), explicit DFMA only
__device__ __forceinline__ void dsincos(double x, float* so, float* co) {
    double n = rint(x * 0.63661977236758138);       // x * 2/pi
    long long qi = (long long)n;
    double r = fma(n, -1.5707963267948966, x);      // pi/2 hi
    r = fma(n, -6.123233995736766e-17, r);          // pi/2 lo
    double r2 = r * r;
    double p = fma(r2, 2.7557319223985893e-06, -1.9841269841269841e-04);
    p = fma(r2, p, 8.3333333333333332e-03);
    p = fma(r2, p, -1.6666666666666666e-01);
    double sinr = fma(r * r2, p, r);
    double q = fma(r2, -2.7557319223985888e-07, 2.4801587301587302e-05);
    q = fma(r2, q, -1.3888888888888889e-03);
    q = fma(r2, q, 4.1666666666666666e-02);
    q = fma(r2, q, -0.5);
    double cosr = fma(r2, q, 1.0);
    switch ((int)(qi & 3)) {
        case 0: *so = (float)sinr;  *co = (float)cosr;  break;
        case 1: *so = (float)cosr;  *co = (float)-sinr; break;
        case 2: *so = (float)-sinr; *co = (float)-cosr; break;
        default:*so = (float)-cosr; *co = (float)sinr;  break;
    }
}

// ---------------- fused prep: f2h(hs) | f2h(Wo) | pack_qkv | rope -----------
// block ranges: [0,1024) hs->Xh, [1024,1536) Wo->Woh, [1536,2304) pack, [2304,2560) rope
#define PREP_BLOCKS 2560

__device__ __forceinline__ void f2h_range(const float* __restrict__ src,
                                          __half* __restrict__ dst,
                                          size_t n4, int blk, int nblk) {
    size_t stride = (size_t)nblk * 256;
    for (size_t i = (size_t)blk * 256 + threadIdx.x; i < n4; i += stride) {
        float4 v = reinterpret_cast<const float4*>(src)[i];
        __half2 h0 = __floats2half2_rn(v.x, v.y);
        __half2 h1 = __floats2half2_rn(v.z, v.w);
        uint2 u;
        u.x = *reinterpret_cast<uint32_t*>(&h0);
        u.y = *reinterpret_cast<uint32_t*>(&h1);
        *reinterpret_cast<uint2*>(dst + i * 4) = u;
    }
}

__global__ __launch_bounds__(256)
void prep_kernel(const float* __restrict__ hs, const float* __restrict__ Wq,
                 const float* __restrict__ Wk, const float* __restrict__ Wv,
                 const float* __restrict__ Wo)
{
    const int b = blockIdx.x;
    if (b < 1024) {
        f2h_range(hs, g_Xh, (size_t)MTOT * HSZ / 4, b, 1024);
    } else if (b < 1536) {
        f2h_range(Wo, g_Woh, (size_t)KD * HSZ / 4, b - 1024, 512);
    } else if (b < 2304) {
        const int blk = b - 1536;
        const size_t total = (size_t)KD * NQKV / 4;
        size_t stride = (size_t)768 * 256;
        for (size_t i = (size_t)blk * 256 + threadIdx.x; i < total; i += stride) {
            int row = (int)(i / (NQKV / 4));
            int col = (int)(i % (NQKV / 4)) * 4;
            float4 v;
            if (col < 4096)
                v = *reinterpret_cast<const float4*>(Wq + (size_t)row * 4096 + col);
            else if (col < 5120)
                v = *reinterpret_cast<const float4*>(Wk + (size_t)row * 1024 + (col - 4096));
            else
                v = *reinterpret_cast<const float4*>(Wv + (size_t)row * 1024 + (col - 5120));
            __half2 h0 = __floats2half2_rn(v.x, v.y);
            __half2 h1 = __floats2half2_rn(v.z, v.w);
            uint2 u;
            u.x = *reinterpret_cast<uint32_t*>(&h0);
            u.y = *reinterpret_cast<uint32_t*>(&h1);
            *reinterpret_cast<uint2*>(g_Wqkvh + (size_t)row * NQKV + col) = u;
        }
    } else {
        // rope: compute emb locally (bit-identical double pow), then table slice
        __shared__ float emb_s[64];
        if (threadIdx.x < 64) {
            int d  = threadIdx.x;
            int k2 = d & ~1;
            float e = (float)k2 / 64.0f;
            emb_s[d] = (float)pow(10000.0, (double)e);
        }
        __syncthreads();
        const int blk = b - 2304;                      // 0..255
        int idx = blk * 1024 + threadIdx.x;            // covers SEQ*64 via 4 steps
        #pragma unroll
        for (int t = 0; t < 4; t++, idx += 256) {
            int pos = idx >> 6, d = idx & 63;
            float emb  = emb_s[d];
            float freq = (float)pos * emb;             // single fp32 rounding, like jax
            float s, c;
            dsincos((double)freq, &s, &c);
            g_sin[idx] = s;
            g_cos[idx] = c;
        }
    }
}

// ---------------- pipelined FP16 GEMM (fp32 accumulate) ----------------------
// C[M,N] = A[M,K] @ B[K,N]. fp16 in. K = 4096.
// CTA tile 128x256, 512 threads (16 warps, 2x8), warp tile 64x32, 3 stages.
// K-loop: 20 branch-free triples (literal slots) + peeled tail; cp.async issue
// interleaved after ks=0 so MMAs start immediately at sync release.
#define BM 128
#define BN 256
#define BK 64
#define NTHR 512
#define STAGES 3
#define PA 72                          // A smem row pitch (halves)
#define PB 264                         // B smem row pitch (halves)
#define A_HALVES (BM * PA)             // 9216
#define B_HALVES (BK * PB)             // 16896
#define STAGE_HALVES (A_HALVES + B_HALVES)
#define STAGE_BYTES (STAGE_HALVES * 2)       // 52224
#define GEMM_DYN (STAGES * STAGE_BYTES)      // 156672
#define NT (KD / BK)                   // 64

template<bool HALF_OUT>
__global__ __launch_bounds__(NTHR, 1)
void gemm_f16(const __half* __restrict__ A, const __half* __restrict__ B,
              void* __restrict__ Cv, int N)
{
    extern __shared__ __half dynh[];
    const uint32_t sbase = s2u(dynh);

    const int tid  = threadIdx.x;
    const int lane = tid & 31, warp = tid >> 5;
    const int warpM = warp & 1;        // 64-row slab
    const int warpN = warp >> 1;       // 0..7 -> 32-col slab
    const int g  = lane >> 2;
    const int tg = lane & 3;

    // L2-friendly mapping: groups of 8 m-tiles across all n-tiles
    const int n_tiles = N / BN;
    const int per = 8 * n_tiles;
    const int gblk = blockIdx.x / per, rr0 = blockIdx.x % per;
    const int mt = gblk * 8 + (rr0 & 7);
    const int nt = rr0 >> 3;
    const int rowBase = mt * BM;
    const int colBase = nt * BN;

    const __half* Ag = A + (size_t)rowBase * KD;

    float c[4][4][4];
    #pragma unroll
    for (int m2 = 0; m2 < 4; m2++)
        #pragma unroll
        for (int n2 = 0; n2 < 4; n2++)
            #pragma unroll
            for (int i = 0; i < 4; i++) c[m2][n2][i] = 0.f;

    // ---- load issuer: K-tile kt -> stage slot s (literal s at call sites)
    auto issue = [&](int kt, int s) {
        const uint32_t sa = sbase + s * STAGE_BYTES;
        const uint32_t sb = sa + A_HALVES * 2;
        #pragma unroll
        for (int i = 0; i < 2; i++) {          // A: 128 rows x 128B = 1024 chunks
            int ch = tid + i * NTHR;
            int r = ch >> 3, c8 = ch & 7;
            cpa16(sa + (r * PA + c8 * 8) * 2,
                  Ag + (size_t)r * KD + kt * BK + c8 * 8);
        }
        #pragma unroll
        for (int i = 0; i < 4; i++) {          // B: 64 rows x 512B = 2048 chunks
            int ch = tid + i * NTHR;
            int r = ch >> 5, c8 = ch & 31;
            cpa16(sb + (r * PB + c8 * 8) * 2,
                  B + (size_t)(kt * BK + r) * N + colBase + c8 * 8);
        }
    };

    issue(0, 0); cpa_commit();
    issue(1, 1); cpa_commit();

    // ldmatrix per-lane byte offsets
    const uint32_t a_off = ((warpM * 64 + (lane & 15)) * PA + (lane >> 4) * 8) * 2;
    const uint32_t b_off = ((lane & 15) * PB + warpN * 32 + (lane >> 4) * 8) * 2;

    // fragment-load + mma for ks range [KS0, KS1) of tile resident at (sa, sb)
    auto compute_r = [&](const uint32_t sa, const uint32_t sb,
                         const int KS0, const int KS1) {
        #pragma unroll
        for (int ks = 0; ks < 4; ks++) {
            if (ks < KS0 || ks >= KS1) continue;
            uint32_t af[4][4], bf[2][4];
            #pragma unroll
            for (int m2 = 0; m2 < 4; m2++)
                ldmA(af[m2], sa + a_off + (m2 * 16 * PA + ks * 16) * 2);
            #pragma unroll
            for (int n4 = 0; n4 < 2; n4++)
                ldmB4(bf[n4], sb + b_off + (ks * 16 * PB + n4 * 16) * 2);
            #pragma unroll
            for (int m2 = 0; m2 < 4; m2++)
                #pragma unroll
                for (int n4 = 0; n4 < 2; n4++) {
                    mma16816(c[m2][n4 * 2    ], af[m2], bf[n4][0], bf[n4][1]);
                    mma16816(c[m2][n4 * 2 + 1], af[m2], bf[n4][2], bf[n4][3]);
                }
        }
    };

    const uint32_t sa0 = sbase;
    const uint32_t sa1 = sbase + STAGE_BYTES;
    const uint32_t sa2 = sbase + 2 * STAGE_BYTES;
    const uint32_t sboff = A_HALVES * 2;

    // main loop: kt 0..59, 20 branch-free triples; issue after ks0 compute
    for (int kt = 0; kt < 60; kt += 3) {
        cpa_wait<1>(); __syncthreads();
        compute_r(sa0, sa0 + sboff, 0, 1);
        issue(kt + 2, 2); cpa_commit();
        compute_r(sa0, sa0 + sboff, 1, 4);

        cpa_wait<1>(); __syncthreads();
        compute_r(sa1, sa1 + sboff, 0, 1);
        issue(kt + 3, 0); cpa_commit();
        compute_r(sa1, sa1 + sboff, 1, 4);

        cpa_wait<1>(); __syncthreads();
        compute_r(sa2, sa2 + sboff, 0, 1);
        issue(kt + 4, 1); cpa_commit();
        compute_r(sa2, sa2 + sboff, 1, 4);
    }
    // kt = 60 (slot 0, issue 62 -> slot 2)
    cpa_wait<1>(); __syncthreads();
    compute_r(sa0, sa0 + sboff, 0, 1);
    issue(62, 2); cpa_commit();
    compute_r(sa0, sa0 + sboff, 1, 4);
    // kt = 61 (slot 1, issue 63 -> slot 0)
    cpa_wait<1>(); __syncthreads();
    compute_r(sa1, sa1 + sboff, 0, 1);
    issue(63, 0); cpa_commit();
    compute_r(sa1, sa1 + sboff, 1, 4);
    // kt = 62 (slot 2, no issue)
    cpa_wait<1>(); __syncthreads();
    compute_r(sa2, sa2 + sboff, 0, 4);
    // kt = 63 (slot 0, no issue; drain all)
    cpa_wait<0>(); __syncthreads();
    compute_r(sa0, sa0 + sboff, 0, 4);

    // epilogue
    #pragma unroll
    for (int m2 = 0; m2 < 4; m2++) {
        #pragma unroll
        for (int n2 = 0; n2 < 4; n2++) {
            int row = rowBase + warpM * 64 + m2 * 16 + g;
            int col = colBase + warpN * 32 + n2 * 8 + tg * 2;
            if (HALF_OUT) {
                __half* C = (__half*)Cv;
                __half2 v01 = __floats2half2_rn(c[m2][n2][0], c[m2][n2][1]);
                __half2 v23 = __floats2half2_rn(c[m2][n2][2], c[m2][n2][3]);
                *reinterpret_cast<__half2*>(C + (size_t)row * N + col)       = v01;
                *reinterpret_cast<__half2*>(C + (size_t)(row + 8) * N + col) = v23;
            } else {
                float* C = (float*)Cv;
                float2 v01 = make_float2(c[m2][n2][0], c[m2][n2][1]);
                float2 v23 = make_float2(c[m2][n2][2], c[m2][n2][3]);
                *reinterpret_cast<float2*>(C + (size_t)row * N + col)       = v01;
                *reinterpret_cast<float2*>(C + (size_t)(row + 8) * N + col) = v23;
            }
        }
    }
}

// ---------------- RoPE + per-token GQA attention -----------------------------
// Q/K staged as fp32 (RoPE'd); V staged as raw half2 bits (pass-through).
__global__ __launch_bounds__(256)
void attn_kernel()
{
    const int tok = blockIdx.x;
    const int pos = tok & (SEQ - 1);
    const int tid = threadIdx.x;

    __shared__ float    qs[NHEADS][HD + 4];
    __shared__ float    ks[NKV][HD + 4];
    __shared__ uint32_t vs2[NKV][64 + 4];    // half2 pairs; [0..31]=dims 0..63, [32..63]=64..127
    __shared__ float    ps[NHEADS][NKV];

    const float* sp = g_sin + pos * 64;
    const float* cp = g_cos + pos * 64;
    const __half* base = g_QKVh + (size_t)tok * NQKV;

    // K/V: NKV*32 threads handle 2 dims each
    for (int idx = tid; idx < NKV * 32; idx += 256) {
        int j = idx >> 5, dd = (idx & 31) * 2;
        const __half* kptr = base + 4096 + j * HD;
        const __half* vptr = base + 5120 + j * HD;
        __half2 klo = *reinterpret_cast<const __half2*>(kptr + dd);
        __half2 khi = *reinterpret_cast<const __half2*>(kptr + 64 + dd);
        uint32_t vlo = *reinterpret_cast<const uint32_t*>(vptr + dd);
        uint32_t vhi = *reinterpret_cast<const uint32_t*>(vptr + 64 + dd);
        vs2[j][dd >> 1]        = vlo;
        vs2[j][32 + (dd >> 1)] = vhi;
        #pragma unroll
        for (int u = 0; u < 2; u++) {
            int d = dd + u;
            float s = sp[d], co = cp[d];
            float k0 = __half2float(u ? __high2half(klo) : __low2half(klo));
            float k1 = __half2float(u ? __high2half(khi) : __low2half(khi));
            ks[j][d]      = k0 * co - k1 * s;
            ks[j][d + 64] = k1 * co + k0 * s;
        }
    }
    // Q: NHEADS*32 threads handle 2 dims each
    for (int idx = tid; idx < NHEADS * 32; idx += 256) {
        int h = idx >> 5, dd = (idx & 31) * 2;
        const __half* qptr = base + h * HD;
        __half2 qlo = *reinterpret_cast<const __half2*>(qptr + dd);
        __half2 qhi = *reinterpret_cast<const __half2*>(qptr + 64 + dd);
        #pragma unroll
        for (int u = 0; u < 2; u++) {
            int d = dd + u;
            float s = sp[d], co = cp[d];
            float q0 = __half2float(u ? __high2half(qlo) : __low2half(qlo));
            float q1 = __half2float(u ? __high2half(qhi) : __low2half(qhi));
            qs[h][d]      = q0 * co - q1 * s;
            qs[h][d + 64] = q1 * co + q0 * s;
        }
    }
    __syncthreads();

    const int h = tid >> 3, j = tid & 7;
    float acc = 0.f;
    #pragma unroll 8
    for (int d = 0; d < HD; d++) acc += qs[h][d] * ks[j][d];
    float sc = acc / sqrtf(128.0f);

    float m = sc;
    m = fmaxf(m, __shfl_xor_sync(0xffffffffu, m, 1));
    m = fmaxf(m, __shfl_xor_sync(0xffffffffu, m, 2));
    m = fmaxf(m, __shfl_xor_sync(0xffffffffu, m, 4));
    float e = expf(sc - m);
    float z = e;
    z += __shfl_xor_sync(0xffffffffu, z, 1);
    z += __shfl_xor_sync(0xffffffffu, z, 2);
    z += __shfl_xor_sync(0xffffffffu, z, 4);
    ps[h][j] = e / z;
    __syncthreads();

    // out: 2 elems per thread per iter; v via raw half2 (identical floats/order)
    #pragma unroll
    for (int it = 0; it < 8; it++) {
        int idx2 = (tid + it * 256) * 2;       // even element index
        int hh = idx2 >> 7, d = idx2 & 127;
        int d2 = d >> 1;
        float a0 = 0.f, a1 = 0.f;
        #pragma unroll
        for (int jj = 0; jj < NKV; jj++) {
            float p = ps[hh][jj];
            uint32_t vb = vs2[jj][d2];
            __half2 v = *reinterpret_cast<__half2*>(&vb);
            a0 += p * __half2float(__low2half(v));
            a1 += p * __half2float(__high2half(v));
        }
        *reinterpret_cast<__half2*>(g_Yh + (size_t)tok * HSZ + idx2) =
            __floats2half2_rn(a0, a1);
    }
}

// ---------------- launch ----------------------------------------------------
extern "C" void kernel_launch(void* const* d_in, const int* in_sizes, int n_in,
                              void* d_out, int out_size)
{
    const float* hs = (const float*)d_in[0];
    const float* Wq = (const float*)d_in[1];
    const float* Wk = (const float*)d_in[2];
    const float* Wv = (const float*)d_in[3];
    const float* Wo = (const float*)d_in[4];
    float* out = (float*)d_out;

    __half *xh, *wqkvh, *woh, *qkvh, *yh;
    cudaGetSymbolAddress((void**)&xh,    g_Xh);
    cudaGetSymbolAddress((void**)&wqkvh, g_Wqkvh);
    cudaGetSymbolAddress((void**)&woh,   g_Woh);
    cudaGetSymbolAddress((void**)&qkvh,  g_QKVh);
    cudaGetSymbolAddress((void**)&yh,    g_Yh);

    cudaFuncSetAttribute(gemm_f16<true>,  cudaFuncAttributeMaxDynamicSharedMemorySize, GEMM_DYN);
    cudaFuncSetAttribute(gemm_f16<false>, cudaFuncAttributeMaxDynamicSharedMemorySize, GEMM_DYN);

    // prep (fused, emb computed in-block)
    prep_kernel<<<PREP_BLOCKS, 256>>>(hs, Wq, Wk, Wv, Wo);

    // fused QKV projection: [8192,4096] @ [4096,6144] -> fp16
    gemm_f16<true><<<(MTOT / BM) * (NQKV / BN), NTHR, GEMM_DYN>>>(xh, wqkvh, qkvh, NQKV);

    attn_kernel<<<MTOT, 256>>>();

    // output projection: [8192,4096] @ [4096,4096] -> fp32 (d_out)
    gemm_f16<false><<<(MTOT / BM) * (HSZ / BN), NTHR, GEMM_DYN>>>(yh, woh, out, HSZ);
}